// round 5
// baseline (speedup 1.0000x reference)
#include <cuda_runtime.h>
#include <math.h>

#define BB 8
#define HH 32
#define DD 128
#define NLL 1
#define NCTA 740      // 148 SMs * 5 CTAs -> one persistent wave at occupancy 5
#define NW 8          // warps per CTA
#define CHUNK 64      // seq positions per work ticket
#define MAXSLOT 64    // max chunks per head (n<=4096)

// Scratch (device allocs forbidden)
__device__ float g_po[BB * HH * MAXSLOT * DD];
__device__ float g_pm[BB * HH * MAXSLOT];
__device__ float g_pl[BB * HH * MAXSLOT];
__device__ int   g_cnt[BB * HH];   // zero-init; self-resetting per head
__device__ int   g_work;           // ticket counter; reset_k zeroes per launch

__global__ void reset_k() { g_work = 0; }

__device__ __forceinline__ float4 ldcs4(const float4* p) { return __ldcs(p); }

__global__ __launch_bounds__(256, 5) void attn_dyn_k(
    const float* __restrict__ qkv,
    const float* __restrict__ kc,
    const float* __restrict__ vc,
    const int* __restrict__ plen,
    const int* __restrict__ playr,
    float* __restrict__ out,
    int Scap)
{
    __shared__ float s_cos[DD / 2];
    __shared__ float s_sin[DD / 2];
    __shared__ float sq[DD];
    __shared__ float sk[DD];
    __shared__ float sm_o[NW][DD];
    __shared__ float sm_m[NW];
    __shared__ float sm_l[NW];
    __shared__ int   s_ticket;
    __shared__ int   s_last;

    const int n = *plen;
    const int Lidx = *playr;
    const int cpHead = (n + CHUNK - 1) / CHUNK;          // chunks per head
    const int total  = BB * HH * cpHead;

    const int tid  = threadIdx.x;
    const int warp = tid >> 5;
    const int lane = tid & 31;
    const float scale = rsqrtf((float)DD);
    const size_t sstride = (size_t)HH * DD;
    const size_t wstep4  = (size_t)NW * sstride / 4;     // warp stride in float4

    // head-invariant RoPE table (position n-1), once per CTA
    if (tid < DD / 2) {
        float inv = powf(10000.0f, -(float)(2 * tid) / (float)DD);
        float fr = (float)(n - 1) * inv;
        sincosf(fr, &s_sin[tid], &s_cos[tid]);
    }
    __syncthreads();

    int prev_bh = -1;

    for (;;) {
        if (tid == 0) s_ticket = atomicAdd(&g_work, 1);
        __syncthreads();
        const int t = s_ticket;
        if (t >= total) break;

        const int bh   = t / cpHead;
        const int slot = t - bh * cpHead;
        const int b = bh / HH, h = bh % HH;

        // ---- head setup: RoPE q,k into smem (only when head changes) ----
        if (bh != prev_bh) {
            if (tid < 128) {
                const int half = tid >> 6;      // 0 = q, 1 = k
                const int i = tid & 63;
                const float cv = s_cos[i], sv = s_sin[i];
                const float* p = qkv + ((size_t)(b * 3 + half) * HH + h) * DD;
                float x0 = p[2 * i], x1 = p[2 * i + 1];
                float* o = half ? sk : sq;
                o[2 * i]     = x0 * cv - x1 * sv;
                o[2 * i + 1] = x1 * cv + x0 * sv;
            }
            prev_bh = bh;
        }
        __syncthreads();

        const float4 qv = ((const float4*)sq)[lane];
        const float* kbase = kc + ((size_t)(b * NLL + Lidx) * Scap) * sstride + (size_t)h * DD;
        const float* vbase = vc + ((size_t)(b * NLL + Lidx) * Scap) * sstride + (size_t)h * DD;

        const int a    = slot * CHUNK;
        const int bpos = min(a + CHUNK, n);
        const int bmain = (bpos == n) ? n - 1 : bpos;

        float m = -INFINITY, l = 0.0f;
        float4 acc = make_float4(0.0f, 0.0f, 0.0f, 0.0f);

        int s = a + warp;
        const float4* kp = (const float4*)(kbase + (size_t)s * sstride) + lane;
        const float4* vp = (const float4*)(vbase + (size_t)s * sstride) + lane;

        // ---- 4-way unrolled main loop: 8 loads front-batched ----
        for (; s + 3 * NW < bmain; s += 4 * NW) {
            float4 k0 = ldcs4(kp);
            float4 k1 = ldcs4(kp + wstep4);
            float4 k2 = ldcs4(kp + 2 * wstep4);
            float4 k3 = ldcs4(kp + 3 * wstep4);
            float4 v0 = ldcs4(vp);
            float4 v1 = ldcs4(vp + wstep4);
            float4 v2 = ldcs4(vp + 2 * wstep4);
            float4 v3 = ldcs4(vp + 3 * wstep4);
            kp += 4 * wstep4;
            vp += 4 * wstep4;

            float d0 = qv.x * k0.x + qv.y * k0.y + qv.z * k0.z + qv.w * k0.w;
            float d1 = qv.x * k1.x + qv.y * k1.y + qv.z * k1.z + qv.w * k1.w;
            float d2 = qv.x * k2.x + qv.y * k2.y + qv.z * k2.z + qv.w * k2.w;
            float d3 = qv.x * k3.x + qv.y * k3.y + qv.z * k3.z + qv.w * k3.w;
            #pragma unroll
            for (int off = 16; off; off >>= 1) {
                d0 += __shfl_xor_sync(0xffffffffu, d0, off);
                d1 += __shfl_xor_sync(0xffffffffu, d1, off);
                d2 += __shfl_xor_sync(0xffffffffu, d2, off);
                d3 += __shfl_xor_sync(0xffffffffu, d3, off);
            }
            d0 *= scale; d1 *= scale; d2 *= scale; d3 *= scale;

            float mnew = fmaxf(fmaxf(fmaxf(m, d0), fmaxf(d1, d2)), d3);
            float corr = __expf(m - mnew);
            float w0 = __expf(d0 - mnew);
            float w1 = __expf(d1 - mnew);
            float w2 = __expf(d2 - mnew);
            float w3 = __expf(d3 - mnew);
            l = l * corr + (w0 + w1) + (w2 + w3);
            acc.x = acc.x * corr + w0 * v0.x + w1 * v1.x + w2 * v2.x + w3 * v3.x;
            acc.y = acc.y * corr + w0 * v0.y + w1 * v1.y + w2 * v2.y + w3 * v3.y;
            acc.z = acc.z * corr + w0 * v0.z + w1 * v1.z + w2 * v2.z + w3 * v3.z;
            acc.w = acc.w * corr + w0 * v0.w + w1 * v1.w + w2 * v2.w + w3 * v3.w;
            m = mnew;
        }
        // ---- tail ----
        for (; s < bmain; s += NW) {
            float4 kv = ldcs4(kp);
            float4 vv = ldcs4(vp);
            kp += wstep4;
            vp += wstep4;
            float d = qv.x * kv.x + qv.y * kv.y + qv.z * kv.z + qv.w * kv.w;
            #pragma unroll
            for (int off = 16; off; off >>= 1)
                d += __shfl_xor_sync(0xffffffffu, d, off);
            d *= scale;
            float mnew = fmaxf(m, d);
            float corr = __expf(m - mnew);
            float w = __expf(d - mnew);
            l = l * corr + w;
            acc.x = acc.x * corr + w * vv.x;
            acc.y = acc.y * corr + w * vv.y;
            acc.z = acc.z * corr + w * vv.z;
            acc.w = acc.w * corr + w * vv.w;
            m = mnew;
        }

        // ---- new position (roped k from smem, v from qkv), warp 0 only ----
        if (bpos == n && warp == 0) {
            float4 kv = ((const float4*)sk)[lane];
            float d = qv.x * kv.x + qv.y * kv.y + qv.z * kv.z + qv.w * kv.w;
            #pragma unroll
            for (int off = 16; off; off >>= 1)
                d += __shfl_xor_sync(0xffffffffu, d, off);
            d *= scale;
            float4 vv = *((const float4*)(qkv + ((size_t)(b * 3 + 2) * HH + h) * DD) + lane);
            float mnew = fmaxf(m, d);
            float corr = __expf(m - mnew);
            float w = __expf(d - mnew);
            l = l * corr + w;
            acc.x = acc.x * corr + w * vv.x;
            acc.y = acc.y * corr + w * vv.y;
            acc.z = acc.z * corr + w * vv.z;
            acc.w = acc.w * corr + w * vv.w;
            m = mnew;
        }

        // ---- block combine of 8 warp partials -> chunk partial ----
        if (lane == 0) { sm_m[warp] = m; sm_l[warp] = l; }
        ((float4*)sm_o[warp])[lane] = acc;
        __syncthreads();

        if (tid < DD) {
            float M = -INFINITY;
            #pragma unroll
            for (int w = 0; w < NW; w++) M = fmaxf(M, sm_m[w]);
            float Ls = 0.0f, o = 0.0f;
            #pragma unroll
            for (int w = 0; w < NW; w++) {
                float mw = sm_m[w];
                float e = (mw == -INFINITY) ? 0.0f : __expf(mw - M);
                Ls += e * sm_l[w];
                o += e * sm_o[w][tid];
            }
            g_po[((size_t)bh * MAXSLOT + slot) * DD + tid] = o;
            if (tid == 0) {
                g_pm[bh * MAXSLOT + slot] = M;
                g_pl[bh * MAXSLOT + slot] = Ls;
            }
        }
        __threadfence();
        __syncthreads();

        if (tid == 0) {
            int old = atomicAdd(&g_cnt[bh], 1);
            int last = (old == cpHead - 1);
            if (last) g_cnt[bh] = 0;           // reset for next replay
            s_last = last;
        }
        __syncthreads();

        if (s_last) {
            __threadfence();
            if (tid < DD) {
                float M = -INFINITY;
                for (int i = 0; i < cpHead; i++)
                    M = fmaxf(M, g_pm[bh * MAXSLOT + i]);
                float Ls = 0.0f, o = 0.0f;
                for (int i = 0; i < cpHead; i++) {
                    float mi = g_pm[bh * MAXSLOT + i];
                    float e = (mi == -INFINITY) ? 0.0f : __expf(mi - M);
                    Ls += e * g_pl[bh * MAXSLOT + i];
                    o += e * g_po[((size_t)bh * MAXSLOT + i) * DD + tid];
                }
                out[(size_t)bh * DD + tid] = o / Ls;
            }
        }
        __syncthreads();
    }
}

extern "C" void kernel_launch(void* const* d_in, const int* in_sizes, int n_in,
                              void* d_out, int out_size) {
    const float* qkv = (const float*)d_in[0];
    const float* kc  = (const float*)d_in[1];
    const float* vc  = (const float*)d_in[2];
    const int* plen  = (const int*)d_in[3];
    const int* playr = (const int*)d_in[4];
    float* out = (float*)d_out;

    int Scap = in_sizes[1] / (BB * NLL * HH * DD);

    reset_k<<<1, 1>>>();
    attn_dyn_k<<<NCTA, 256>>>(qkv, kc, vc, plen, playr, out, Scap);
}

// round 6
// speedup vs baseline: 1.1096x; 1.1096x over previous
#include <cuda_runtime.h>
#include <math.h>

#define BB 8
#define HH 32
#define DD 128
#define NLL 1
#define NCTA 296      // 148 SMs * 2 CTAs, one wave at occupancy 2
#define MAXSLOT 64

// Scratch (device allocs forbidden)
__device__ __align__(16) float g_po[(size_t)BB * MAXSLOT * HH * DD];
__device__ float g_pm[BB * MAXSLOT * HH];
__device__ float g_pl[BB * MAXSLOT * HH];

__device__ __forceinline__ int cta_of(long long p, long long base, long long rem) {
    long long thr = rem * (base + 1);
    if (p < thr) return (int)(p / (base + 1));
    return (int)(rem + (p - thr) / base);
}

// One CTA = all 32 heads of one batch over a position range.
// Warp w -> heads 4w..4w+3. Load instr i = head 4w+i row, fully coalesced.
__global__ __launch_bounds__(256, 2) void attn_batch_k(
    const float* __restrict__ qkv,
    const float* __restrict__ kc,
    const float* __restrict__ vc,
    const int* __restrict__ plen,
    const int* __restrict__ playr,
    int Scap)
{
    __shared__ float s_cos[DD / 2], s_sin[DD / 2];

    const int n = *plen;
    const int Lidx = *playr;
    const int nm = n - 1;                      // streamed positions per batch
    const long long P = (long long)BB * nm;
    const long long base = P / NCTA;
    const long long rem  = P - base * NCTA;

    const int cta = blockIdx.x;
    const long long start = (long long)cta * base + min((long long)cta, rem);
    const long long end   = start + base + ((long long)cta < rem ? 1 : 0);

    const int tid  = threadIdx.x;
    const int warp = tid >> 5;
    const int lane = tid & 31;
    const int h0   = warp * 4;
    const float scale = rsqrtf((float)DD);

    if (tid < DD / 2) {
        float inv = powf(10000.0f, -(float)(2 * tid) / (float)DD);
        float fr = (float)(n - 1) * inv;
        sincosf(fr, &s_sin[tid], &s_cos[tid]);
    }
    __syncthreads();

    // thread's float4 covers dims [lane*4, lane*4+4) -> rope pairs lane*2, lane*2+1
    const float c0 = s_cos[lane * 2],     sn0 = s_sin[lane * 2];
    const float c1 = s_cos[lane * 2 + 1], sn1 = s_sin[lane * 2 + 1];

    const int b0 = (int)(start / nm);
    const int b1 = (int)((end - 1) / nm);

    for (int b = b0; b <= b1; b++) {
        const int a = (int)(max(start, (long long)b * nm) - (long long)b * nm);
        const int e = (int)(min(end, (long long)(b + 1) * nm) - (long long)b * nm);
        const bool last_owner = (e == nm);

        // roped q for this warp's 4 heads
        float4 q[4];
        #pragma unroll
        for (int i = 0; i < 4; i++) {
            float4 x = *((const float4*)(qkv + ((size_t)(b * 3 + 0) * HH + h0 + i) * DD) + lane);
            q[i].x = x.x * c0 - x.y * sn0;
            q[i].y = x.y * c0 + x.x * sn0;
            q[i].z = x.z * c1 - x.w * sn1;
            q[i].w = x.w * c1 + x.z * sn1;
        }

        const float4* kr = (const float4*)(kc + ((size_t)(b * NLL + Lidx) * Scap) * HH * DD)
                           + (size_t)a * (HH * DD / 4) + h0 * (DD / 4) + lane;
        const float4* vr = (const float4*)(vc + ((size_t)(b * NLL + Lidx) * Scap) * HH * DD)
                           + (size_t)a * (HH * DD / 4) + h0 * (DD / 4) + lane;

        float  m[4] = {-INFINITY, -INFINITY, -INFINITY, -INFINITY};
        float  l[4] = {0.f, 0.f, 0.f, 0.f};
        float4 acc[4];
        #pragma unroll
        for (int i = 0; i < 4; i++) acc[i] = make_float4(0.f, 0.f, 0.f, 0.f);

        float4 KA[4], VA[4], KB[4], VB[4];

#define LOADN(KX, VX) do {                                                    \
            KX[0] = __ldcs(kr);      KX[1] = __ldcs(kr + 32);                 \
            KX[2] = __ldcs(kr + 64); KX[3] = __ldcs(kr + 96);                 \
            VX[0] = __ldcs(vr);      VX[1] = __ldcs(vr + 32);                 \
            VX[2] = __ldcs(vr + 64); VX[3] = __ldcs(vr + 96);                 \
            kr += (HH * DD / 4); vr += (HH * DD / 4);                         \
        } while (0)

#define STEP(KX, VX) do {                                                     \
            float dd[4];                                                      \
            _Pragma("unroll")                                                 \
            for (int i = 0; i < 4; i++)                                       \
                dd[i] = q[i].x * KX[i].x + q[i].y * KX[i].y                   \
                      + q[i].z * KX[i].z + q[i].w * KX[i].w;                  \
            _Pragma("unroll")                                                 \
            for (int off = 16; off; off >>= 1) {                              \
                dd[0] += __shfl_xor_sync(0xffffffffu, dd[0], off);            \
                dd[1] += __shfl_xor_sync(0xffffffffu, dd[1], off);            \
                dd[2] += __shfl_xor_sync(0xffffffffu, dd[2], off);            \
                dd[3] += __shfl_xor_sync(0xffffffffu, dd[3], off);            \
            }                                                                 \
            _Pragma("unroll")                                                 \
            for (int i = 0; i < 4; i++) {                                     \
                float d = dd[i] * scale;                                      \
                float mn = fmaxf(m[i], d);                                    \
                float corr = __expf(m[i] - mn);                               \
                float w = __expf(d - mn);                                     \
                l[i] = l[i] * corr + w;                                       \
                acc[i].x = acc[i].x * corr + w * VX[i].x;                     \
                acc[i].y = acc[i].y * corr + w * VX[i].y;                     \
                acc[i].z = acc[i].z * corr + w * VX[i].z;                     \
                acc[i].w = acc[i].w * corr + w * VX[i].w;                     \
                m[i] = mn;                                                    \
            }                                                                 \
        } while (0)

        if (a < e) {
            LOADN(KA, VA);                 // pos a
            int s = a;
            for (; s + 1 < e; s += 2) {
                LOADN(KB, VB);             // pos s+1
                STEP(KA, VA);              // compute pos s
                if (s + 2 < e) LOADN(KA, VA);
                STEP(KB, VB);              // compute pos s+1
            }
            if (s < e) STEP(KA, VA);       // odd tail
        }

        // new position n-1: roped k + v straight from qkv
        if (last_owner) {
            float4 kk[4], vv[4];
            #pragma unroll
            for (int i = 0; i < 4; i++) {
                float4 x = *((const float4*)(qkv + ((size_t)(b * 3 + 1) * HH + h0 + i) * DD) + lane);
                kk[i].x = x.x * c0 - x.y * sn0;
                kk[i].y = x.y * c0 + x.x * sn0;
                kk[i].z = x.z * c1 - x.w * sn1;
                kk[i].w = x.w * c1 + x.z * sn1;
                vv[i] = *((const float4*)(qkv + ((size_t)(b * 3 + 2) * HH + h0 + i) * DD) + lane);
            }
            STEP(kk, vv);
        }
#undef LOADN
#undef STEP

        // write partials
        const int slot = cta - cta_of((long long)b * nm, base, rem);
        #pragma unroll
        for (int i = 0; i < 4; i++)
            *((float4*)(g_po + (((size_t)b * MAXSLOT + slot) * HH + h0 + i) * DD) + lane) = acc[i];
        if (lane < 4) {
            float mv = lane == 0 ? m[0] : lane == 1 ? m[1] : lane == 2 ? m[2] : m[3];
            float lv = lane == 0 ? l[0] : lane == 1 ? l[1] : lane == 2 ? l[2] : l[3];
            g_pm[((size_t)b * MAXSLOT + slot) * HH + h0 + lane] = mv;
            g_pl[((size_t)b * MAXSLOT + slot) * HH + h0 + lane] = lv;
        }
    }
}

// Combine per-(b,h) partials across the CTAs that covered batch b.
__global__ void reduce2_k(float* __restrict__ out, const int* __restrict__ plen) {
    const int bh = blockIdx.x;
    const int b = bh >> 5, h = bh & 31;
    const int d = threadIdx.x;
    const int n = *plen;
    const int nm = n - 1;
    const long long P = (long long)BB * nm;
    const long long base = P / NCTA;
    const long long rem  = P - base * NCTA;

    const int cfirst = cta_of((long long)b * nm, base, rem);
    const int clast  = cta_of((long long)(b + 1) * nm - 1, base, rem);
    const int ns = clast - cfirst + 1;

    float M = -INFINITY;
    for (int s = 0; s < ns; s++)
        M = fmaxf(M, g_pm[((size_t)b * MAXSLOT + s) * HH + h]);

    float L = 0.f, o = 0.f;
    for (int s = 0; s < ns; s++) {
        float e = __expf(g_pm[((size_t)b * MAXSLOT + s) * HH + h] - M);
        L += e * g_pl[((size_t)b * MAXSLOT + s) * HH + h];
        o += e * g_po[(((size_t)b * MAXSLOT + s) * HH + h) * DD + d];
    }
    out[(size_t)bh * DD + d] = o / L;
}

extern "C" void kernel_launch(void* const* d_in, const int* in_sizes, int n_in,
                              void* d_out, int out_size) {
    const float* qkv = (const float*)d_in[0];
    const float* kc  = (const float*)d_in[1];
    const float* vc  = (const float*)d_in[2];
    const int* plen  = (const int*)d_in[3];
    const int* playr = (const int*)d_in[4];
    float* out = (float*)d_out;

    int Scap = in_sizes[1] / (BB * NLL * HH * DD);

    attn_batch_k<<<NCTA, 256>>>(qkv, kc, vc, plen, playr, Scap);
    reduce2_k<<<BB * HH, 128>>>(out, plen);
}

// round 7
// speedup vs baseline: 1.1384x; 1.0260x over previous
#include <cuda_runtime.h>
#include <math.h>

#define BB 8
#define HH 32
#define DD 128
#define NLL 1
#define NCTA 296      // 148 SMs * 2 CTAs, one wave at occupancy 2
#define MAXSLOT 64
#define RGRP 8        // slot groups in the reducer

// Scratch (device allocs forbidden)
__device__ __align__(16) float g_po[(size_t)BB * MAXSLOT * HH * DD];
__device__ float g_pm[BB * MAXSLOT * HH];
__device__ float g_pl[BB * MAXSLOT * HH];

__device__ __forceinline__ int cta_of(long long p, long long base, long long rem) {
    long long thr = rem * (base + 1);
    if (p < thr) return (int)(p / (base + 1));
    return (int)(rem + (p - thr) / base);
}

// One CTA = all 32 heads of one batch over a position range.
// Warp w -> heads 4w..4w+3. Load instr i = head 4w+i row, fully coalesced.
__global__ __launch_bounds__(256, 2) void attn_batch_k(
    const float* __restrict__ qkv,
    const float* __restrict__ kc,
    const float* __restrict__ vc,
    const int* __restrict__ plen,
    const int* __restrict__ playr,
    int Scap)
{
    __shared__ float s_cos[DD / 2], s_sin[DD / 2];

    const int n = *plen;
    const int Lidx = *playr;
    const int nm = n - 1;                      // streamed positions per batch
    const long long P = (long long)BB * nm;
    const long long base = P / NCTA;
    const long long rem  = P - base * NCTA;

    const int cta = blockIdx.x;
    const long long start = (long long)cta * base + min((long long)cta, rem);
    const long long end   = start + base + ((long long)cta < rem ? 1 : 0);

    const int tid  = threadIdx.x;
    const int warp = tid >> 5;
    const int lane = tid & 31;
    const int h0   = warp * 4;
    const float scale = rsqrtf((float)DD);

    if (tid < DD / 2) {
        float inv = powf(10000.0f, -(float)(2 * tid) / (float)DD);
        float fr = (float)(n - 1) * inv;
        sincosf(fr, &s_sin[tid], &s_cos[tid]);
    }
    __syncthreads();

    // thread's float4 covers dims [lane*4, lane*4+4) -> rope pairs lane*2, lane*2+1
    const float c0 = s_cos[lane * 2],     sn0 = s_sin[lane * 2];
    const float c1 = s_cos[lane * 2 + 1], sn1 = s_sin[lane * 2 + 1];

    const int b0 = (int)(start / nm);
    const int b1 = (int)((end - 1) / nm);

    for (int b = b0; b <= b1; b++) {
        const int a = (int)(max(start, (long long)b * nm) - (long long)b * nm);
        const int e = (int)(min(end, (long long)(b + 1) * nm) - (long long)b * nm);
        const bool last_owner = (e == nm);

        // roped q for this warp's 4 heads
        float4 q[4];
        #pragma unroll
        for (int i = 0; i < 4; i++) {
            float4 x = *((const float4*)(qkv + ((size_t)(b * 3 + 0) * HH + h0 + i) * DD) + lane);
            q[i].x = x.x * c0 - x.y * sn0;
            q[i].y = x.y * c0 + x.x * sn0;
            q[i].z = x.z * c1 - x.w * sn1;
            q[i].w = x.w * c1 + x.z * sn1;
        }

        const float4* kr = (const float4*)(kc + ((size_t)(b * NLL + Lidx) * Scap) * HH * DD)
                           + (size_t)a * (HH * DD / 4) + h0 * (DD / 4) + lane;
        const float4* vr = (const float4*)(vc + ((size_t)(b * NLL + Lidx) * Scap) * HH * DD)
                           + (size_t)a * (HH * DD / 4) + h0 * (DD / 4) + lane;

        float  m[4] = {-INFINITY, -INFINITY, -INFINITY, -INFINITY};
        float  l[4] = {0.f, 0.f, 0.f, 0.f};
        float4 acc[4];
        #pragma unroll
        for (int i = 0; i < 4; i++) acc[i] = make_float4(0.f, 0.f, 0.f, 0.f);

        float4 KA[4], VA[4], KB[4], VB[4];

#define LOADN(KX, VX) do {                                                    \
            KX[0] = __ldcs(kr);      KX[1] = __ldcs(kr + 32);                 \
            KX[2] = __ldcs(kr + 64); KX[3] = __ldcs(kr + 96);                 \
            VX[0] = __ldcs(vr);      VX[1] = __ldcs(vr + 32);                 \
            VX[2] = __ldcs(vr + 64); VX[3] = __ldcs(vr + 96);                 \
            kr += (HH * DD / 4); vr += (HH * DD / 4);                         \
        } while (0)

#define STEP(KX, VX) do {                                                     \
            float dd[4];                                                      \
            _Pragma("unroll")                                                 \
            for (int i = 0; i < 4; i++)                                       \
                dd[i] = q[i].x * KX[i].x + q[i].y * KX[i].y                   \
                      + q[i].z * KX[i].z + q[i].w * KX[i].w;                  \
            _Pragma("unroll")                                                 \
            for (int off = 16; off; off >>= 1) {                              \
                dd[0] += __shfl_xor_sync(0xffffffffu, dd[0], off);            \
                dd[1] += __shfl_xor_sync(0xffffffffu, dd[1], off);            \
                dd[2] += __shfl_xor_sync(0xffffffffu, dd[2], off);            \
                dd[3] += __shfl_xor_sync(0xffffffffu, dd[3], off);            \
            }                                                                 \
            _Pragma("unroll")                                                 \
            for (int i = 0; i < 4; i++) {                                     \
                float d = dd[i] * scale;                                      \
                float mn = fmaxf(m[i], d);                                    \
                float corr = __expf(m[i] - mn);                               \
                float w = __expf(d - mn);                                     \
                l[i] = l[i] * corr + w;                                       \
                acc[i].x = acc[i].x * corr + w * VX[i].x;                     \
                acc[i].y = acc[i].y * corr + w * VX[i].y;                     \
                acc[i].z = acc[i].z * corr + w * VX[i].z;                     \
                acc[i].w = acc[i].w * corr + w * VX[i].w;                     \
                m[i] = mn;                                                    \
            }                                                                 \
        } while (0)

        if (a < e) {
            LOADN(KA, VA);                 // pos a
            int s = a;
            for (; s + 1 < e; s += 2) {
                LOADN(KB, VB);             // pos s+1
                STEP(KA, VA);              // compute pos s
                if (s + 2 < e) LOADN(KA, VA);
                STEP(KB, VB);              // compute pos s+1
            }
            if (s < e) STEP(KA, VA);       // odd tail
        }

        // new position n-1: roped k + v straight from qkv
        if (last_owner) {
            float4 kk[4], vv[4];
            #pragma unroll
            for (int i = 0; i < 4; i++) {
                float4 x = *((const float4*)(qkv + ((size_t)(b * 3 + 1) * HH + h0 + i) * DD) + lane);
                kk[i].x = x.x * c0 - x.y * sn0;
                kk[i].y = x.y * c0 + x.x * sn0;
                kk[i].z = x.z * c1 - x.w * sn1;
                kk[i].w = x.w * c1 + x.z * sn1;
                vv[i] = *((const float4*)(qkv + ((size_t)(b * 3 + 2) * HH + h0 + i) * DD) + lane);
            }
            STEP(kk, vv);
        }
#undef LOADN
#undef STEP

        // write partials
        const int slot = cta - cta_of((long long)b * nm, base, rem);
        #pragma unroll
        for (int i = 0; i < 4; i++)
            *((float4*)(g_po + (((size_t)b * MAXSLOT + slot) * HH + h0 + i) * DD) + lane) = acc[i];
        if (lane < 4) {
            float mv = lane == 0 ? m[0] : lane == 1 ? m[1] : lane == 2 ? m[2] : m[3];
            float lv = lane == 0 ? l[0] : lane == 1 ? l[1] : lane == 2 ? l[2] : l[3];
            g_pm[((size_t)b * MAXSLOT + slot) * HH + h0 + lane] = mv;
            g_pl[((size_t)b * MAXSLOT + slot) * HH + h0 + lane] = lv;
        }
    }
}

// Parallel combine: one block per (b,h), 1024 threads = RGRP slot-groups x 128 dims.
__global__ __launch_bounds__(1024) void reduce3_k(
    float* __restrict__ out, const int* __restrict__ plen)
{
    __shared__ float sm[MAXSLOT], sl[MAXSLOT];
    __shared__ float pO[RGRP][DD];
    __shared__ float pL[RGRP];

    const int bh = blockIdx.x;
    const int b = bh >> 5, h = bh & 31;
    const int tid = threadIdx.x;
    const int g = tid >> 7;          // slot group 0..7
    const int d = tid & 127;         // output dim

    const int n = *plen;
    const int nm = n - 1;
    const long long P = (long long)BB * nm;
    const long long base = P / NCTA;
    const long long rem  = P - base * NCTA;

    const int cfirst = cta_of((long long)b * nm, base, rem);
    const int clast  = cta_of((long long)(b + 1) * nm - 1, base, rem);
    const int ns = clast - cfirst + 1;

    if (tid < ns) {
        sm[tid] = g_pm[((size_t)b * MAXSLOT + tid) * HH + h];
        sl[tid] = g_pl[((size_t)b * MAXSLOT + tid) * HH + h];
    }
    __syncthreads();

    float M = -INFINITY;
    for (int s = 0; s < ns; s++) M = fmaxf(M, sm[s]);

    float L = 0.f, o = 0.f;
    for (int s = g; s < ns; s += RGRP) {
        float e = __expf(sm[s] - M);
        L += e * sl[s];
        o += e * g_po[(((size_t)b * MAXSLOT + s) * HH + h) * DD + d];
    }
    pO[g][d] = o;
    if (d == 0) pL[g] = L;
    __syncthreads();

    if (g == 0) {
        float Lt = 0.f, ot = 0.f;
        #pragma unroll
        for (int i = 0; i < RGRP; i++) { Lt += pL[i]; ot += pO[i][d]; }
        out[(size_t)bh * DD + d] = ot / Lt;
    }
}

extern "C" void kernel_launch(void* const* d_in, const int* in_sizes, int n_in,
                              void* d_out, int out_size) {
    const float* qkv = (const float*)d_in[0];
    const float* kc  = (const float*)d_in[1];
    const float* vc  = (const float*)d_in[2];
    const int* plen  = (const int*)d_in[3];
    const int* playr = (const int*)d_in[4];
    float* out = (float*)d_out;

    int Scap = in_sizes[1] / (BB * NLL * HH * DD);

    attn_batch_k<<<NCTA, 256>>>(qkv, kc, vc, plen, playr, Scap);
    reduce3_k<<<BB * HH, 1024>>>(out, plen);
}